// round 15
// baseline (speedup 1.0000x reference)
#include <cuda_runtime.h>
#include <cuda_fp16.h>
#include <math.h>
#include <stdint.h>

#define NE 8
#define H 1024
#define F 3584
#define T 4096

#define BM 256
#define BK 32              // halves of K per mainloop iter (2 k16 slices)
#define MT (T / BM)        // 16 m-tiles per expert

// smem strides in 32-bit words (each word = 2 halves)
#define ASTR 20            // 16 data words + 4 pad
#define A_WORDS (BM * ASTR)          // 5120
#define BUSTR 36
#define BU_WORDS (BK * BUSTR)        // 1152
#define BDSTR 68
#define BD_WORDS (BK * BDSTR)        // 2176

// 3-stage pipelines
#define UPG_STAGE (A_WORDS + 2 * BU_WORDS)          // 7424 words (29696 B)
#define DWN_STAGE (A_WORDS + BD_WORDS)              // 7296 words (29184 B)
#define SMEM_UPG (3 * UPG_STAGE * 4)                // 89088 B
#define SMEM_DWN (3 * DWN_STAGE * 4)                // 87552 B

// ---------------- scratch (device globals) ----------------
__device__ int    g_count[NE];
__device__ int    g_idx[NE * T];
__device__ float  g_wt[NE * T];
__device__ __half g_act[(size_t)NE * T * F];
__device__ __half g_wu_h[(size_t)NE * H * F];
__device__ __half g_wg_h[(size_t)NE * H * F];
__device__ __half g_wd_h[(size_t)NE * F * H];
__device__ __half g_x_h[(size_t)T * H];

// ---------------- helpers ----------------
__device__ __forceinline__ uint32_t smem_u32(const void* p) {
    uint32_t a;
    asm("{ .reg .u64 t; cvta.to.shared.u64 t, %1; cvt.u32.u64 %0, t; }" : "=r"(a) : "l"(p));
    return a;
}
__device__ __forceinline__ void cp16(uint32_t dst, const void* src) {
    asm volatile("cp.async.cg.shared.global [%0], [%1], 16;" :: "r"(dst), "l"(src));
}
#define CP_COMMIT() asm volatile("cp.async.commit_group;" ::: "memory")
#define CP_WAIT1()  asm volatile("cp.async.wait_group 1;" ::: "memory")

__device__ __forceinline__ void ldm_x4(uint32_t* r, uint32_t addr) {
    asm volatile("ldmatrix.sync.aligned.m8n8.x4.shared.b16 {%0,%1,%2,%3}, [%4];"
        : "=r"(r[0]), "=r"(r[1]), "=r"(r[2]), "=r"(r[3]) : "r"(addr));
}
__device__ __forceinline__ void ldm_x4t(uint32_t* r, uint32_t addr) {
    asm volatile("ldmatrix.sync.aligned.m8n8.x4.trans.shared.b16 {%0,%1,%2,%3}, [%4];"
        : "=r"(r[0]), "=r"(r[1]), "=r"(r[2]), "=r"(r[3]) : "r"(addr));
}
__device__ __forceinline__ void mma16(float* d, const uint32_t* a, const uint32_t* b) {
    asm volatile(
        "mma.sync.aligned.m16n8k16.row.col.f32.f16.f16.f32 "
        "{%0,%1,%2,%3},{%4,%5,%6,%7},{%8,%9},{%0,%1,%2,%3};"
        : "+f"(d[0]), "+f"(d[1]), "+f"(d[2]), "+f"(d[3])
        : "r"(a[0]), "r"(a[1]), "r"(a[2]), "r"(a[3]), "r"(b[0]), "r"(b[1]));
}

// ---------------- kernel 0: zero y + counters ----------------
__global__ void zero_kernel(float* __restrict__ y) {
    size_t n = (size_t)T * H;
    size_t stride = (size_t)gridDim.x * blockDim.x;
    for (size_t i = (size_t)blockIdx.x * blockDim.x + threadIdx.x; i < n; i += stride)
        y[i] = 0.0f;
    if (blockIdx.x == 0 && threadIdx.x < NE) g_count[threadIdx.x] = 0;
}

// ---------------- kernel: fp32 -> fp16 pre-convert (weights) ----------------
__global__ void cvth_kernel(const float4* __restrict__ src, uint2* __restrict__ dst, int n4) {
    int stride = gridDim.x * blockDim.x;
    for (int i = blockIdx.x * blockDim.x + threadIdx.x; i < n4; i += stride) {
        float4 v = src[i];
        __half2 h0 = __floats2half2_rn(v.x, v.y);
        __half2 h1 = __floats2half2_rn(v.z, v.w);
        uint2 o;
        o.x = *(uint32_t*)&h0;
        o.y = *(uint32_t*)&h1;
        dst[i] = o;
    }
}

// ---------------- kernel 1: router (fp32) + x fp16 convert fused ----------------
__global__ void router_kernel(const float* __restrict__ x,
                              const float* __restrict__ gw,
                              float* __restrict__ logits_out,
                              int write_logits) {
    int warp = threadIdx.x >> 5;
    int lane = threadIdx.x & 31;
    int t = blockIdx.x * 4 + warp;
    if (t >= T) return;
    const float* xr = x + (size_t)t * H;
    __half* xh = g_x_h + (size_t)t * H;

    float acc[NE];
#pragma unroll
    for (int e = 0; e < NE; e++) acc[e] = 0.0f;
    for (int k = lane; k < H; k += 32) {
        float xv = xr[k];
        xh[k] = __float2half_rn(xv);
        const float* g = gw + (size_t)k * NE;
#pragma unroll
        for (int e = 0; e < NE; e++) acc[e] += xv * g[e];
    }
#pragma unroll
    for (int off = 16; off > 0; off >>= 1)
#pragma unroll
        for (int e = 0; e < NE; e++)
            acc[e] += __shfl_down_sync(0xffffffffu, acc[e], off);

    if (lane == 0) {
        if (write_logits) {
#pragma unroll
            for (int e = 0; e < NE; e++) logits_out[(size_t)t * NE + e] = acc[e];
        }
        int i1 = 0;
#pragma unroll
        for (int e = 1; e < NE; e++) if (acc[e] > acc[i1]) i1 = e;
        int i2 = (i1 == 0) ? 1 : 0;
#pragma unroll
        for (int e = 0; e < NE; e++)
            if (e != i1 && acc[e] > acc[i2]) i2 = e;
        float w1 = 1.0f / (1.0f + expf(acc[i2] - acc[i1]));
        float w2 = 1.0f / (1.0f + expf(acc[i1] - acc[i2]));
        int p1 = atomicAdd(&g_count[i1], 1);
        g_idx[i1 * T + p1] = t; g_wt[i1 * T + p1] = w1;
        int p2 = atomicAdd(&g_count[i2], 1);
        g_idx[i2 * T + p2] = t; g_wt[i2 * T + p2] = w2;
    }
}

// ---------------- kernel 2: fp16 up+gate GEMM + SiLU ----------------
// 256 threads, 8 warps (4x2), block tile 256x64 per matrix, warp tile 64x32 per matrix.
// BK=32, 3-stage cp.async pipeline. BM=256 halves weight L2 re-reads.
__global__ __launch_bounds__(256, 1) void upgate_kernel() {
    extern __shared__ uint32_t sm[];
    __shared__ int toks[BM];

    int e = blockIdx.x / MT;
    int mtile = blockIdx.x % MT;
    int cnt = g_count[e];
    int row0 = mtile * BM;
    if (row0 >= cnt) return;
    int f0 = blockIdx.y * 64;

    int tid = threadIdx.x;
    if (tid < BM) {
        int r = row0 + tid;
        toks[tid] = (r < cnt) ? g_idx[e * T + r] : g_idx[e * T];
    }
    __syncthreads();

    const __half* Wu = g_wu_h + (size_t)e * H * F + f0;
    const __half* Wg = g_wg_h + (size_t)e * H * F + f0;

    uint32_t base = smem_u32(sm);

    auto loadStage = [&](int s, int kn) {
        uint32_t ad = base + (s * UPG_STAGE) * 4;
        uint32_t ud = ad + A_WORDS * 4;
        uint32_t gd = ud + BU_WORDS * 4;
        // A: 256 rows x 4 chunks (16B = 8 halves) = 1024 -> 4/thread
#pragma unroll
        for (int j = 0; j < 4; j++) {
            int c = tid + j * 256;
            int m = c >> 2, seg = c & 3;
            cp16(ad + (m * ASTR + seg * 4) * 4,
                 g_x_h + (size_t)toks[m] * H + kn + seg * 8);
        }
        // B: 32 k-rows x 8 chunks = 256 per mat -> 1/thread each
        {
            int kk = tid >> 3, seg = tid & 7;
            uint32_t off = (kk * BUSTR + seg * 4) * 4;
            size_t gi = (size_t)(kn + kk) * F + seg * 8;
            cp16(ud + off, Wu + gi);
            cp16(gd + off, Wg + gi);
        }
    };

    loadStage(0, 0); CP_COMMIT();
    loadStage(1, BK); CP_COMMIT();

    int wid = tid >> 5, lane = tid & 31;
    int wr = (wid >> 1) * 64;      // 0,64,128,192
    int wn = (wid & 1) * 32;       // 0 or 32
    int qr = lane >> 2, qc = lane & 3;

    int lRow = lane & 15;
    int lHi  = (lane & 16) ? 4 : 0;
    uint32_t aLane = ((wr + lRow) * ASTR + lHi) * 4;
    uint32_t bLane = (lRow * BUSTR + (wn >> 1) + lHi) * 4;

    float accU[4][4][4], accG[4][4][4];
#pragma unroll
    for (int mt = 0; mt < 4; mt++)
#pragma unroll
        for (int nt = 0; nt < 4; nt++)
#pragma unroll
            for (int i = 0; i < 4; i++) { accU[mt][nt][i] = 0.0f; accG[mt][nt][i] = 0.0f; }

    const int NIT = H / BK;   // 32
    int s = 0;
    for (int i = 0; i < NIT; i++) {
        CP_WAIT1();
        __syncthreads();

        uint32_t aB = base + (s * UPG_STAGE) * 4 + aLane;
        uint32_t uB = base + (s * UPG_STAGE + A_WORDS) * 4 + bLane;
        uint32_t gB = base + (s * UPG_STAGE + A_WORDS + BU_WORDS) * 4 + bLane;
#pragma unroll
        for (int ks = 0; ks < 2; ks++) {
            uint32_t a[4][4];
#pragma unroll
            for (int mt = 0; mt < 4; mt++)
                ldm_x4(a[mt], aB + (mt * 16 * ASTR + ks * 8) * 4);
            uint32_t bu[2][4], bg[2][4];
#pragma unroll
            for (int ntp = 0; ntp < 2; ntp++) {
                uint32_t koff = (ks * 16 * BUSTR + ntp * 8) * 4;
                ldm_x4t(bu[ntp], uB + koff);
                ldm_x4t(bg[ntp], gB + koff);
            }
#pragma unroll
            for (int mt = 0; mt < 4; mt++)
#pragma unroll
                for (int ntp = 0; ntp < 2; ntp++) {
                    mma16(accU[mt][ntp * 2 + 0], a[mt], &bu[ntp][0]);
                    mma16(accU[mt][ntp * 2 + 1], a[mt], &bu[ntp][2]);
                    mma16(accG[mt][ntp * 2 + 0], a[mt], &bg[ntp][0]);
                    mma16(accG[mt][ntp * 2 + 1], a[mt], &bg[ntp][2]);
                }
        }
        if (i + 2 < NIT) {
            int sn = (s + 2) % 3;
            loadStage(sn, (i + 2) * BK);
        }
        CP_COMMIT();
        s = (s + 1) % 3;
    }

    // epilogue: silu(up)*gate -> g_act (fp16)
#pragma unroll
    for (int mt = 0; mt < 4; mt++)
#pragma unroll
        for (int nt = 0; nt < 4; nt++) {
            int col = f0 + wn + nt * 8 + 2 * qc;
#pragma unroll
            for (int h = 0; h < 2; h++) {
                int r = row0 + wr + mt * 16 + qr + h * 8;
                if (r >= cnt) continue;
                float u0 = accU[mt][nt][h * 2 + 0], u1 = accU[mt][nt][h * 2 + 1];
                float g0 = accG[mt][nt][h * 2 + 0], g1 = accG[mt][nt][h * 2 + 1];
                float s0 = u0 / (1.0f + expf(-u0)) * g0;
                float s1 = u1 / (1.0f + expf(-u1)) * g1;
                *(__half2*)(g_act + ((size_t)e * T + r) * F + col) = __floats2half2_rn(s0, s1);
            }
        }
}

// ---------------- kernel 3: fp16 down GEMM + weighted scatter ----------------
// 256 threads, 8 warps (4x2), block tile 256x128, warp tile 64x64.
// BK=32, 3-stage pipeline. BM=256 halves weight L2 re-reads.
__global__ __launch_bounds__(256, 1) void down_kernel(float* __restrict__ y) {
    extern __shared__ uint32_t sm[];

    int e = blockIdx.x / MT;
    int mtile = blockIdx.x % MT;
    int cnt = g_count[e];
    int row0 = mtile * BM;
    if (row0 >= cnt) return;
    int n0 = blockIdx.y * 128;

    const __half* A = g_act + ((size_t)e * T + row0) * F;
    const __half* W = g_wd_h + (size_t)e * F * H + n0;

    int tid = threadIdx.x;
    uint32_t base = smem_u32(sm);

    auto loadStage = [&](int s, int kn) {
        uint32_t ad = base + (s * DWN_STAGE) * 4;
        uint32_t bd = ad + A_WORDS * 4;
        // A: 1024 chunks -> 4/thread
#pragma unroll
        for (int j = 0; j < 4; j++) {
            int c = tid + j * 256;
            int m = c >> 2, seg = c & 3;
            cp16(ad + (m * ASTR + seg * 4) * 4,
                 A + (size_t)m * F + kn + seg * 8);
        }
        // B: 32 k-rows x 16 chunks = 512 -> 2/thread
#pragma unroll
        for (int j = 0; j < 2; j++) {
            int c = tid + j * 256;
            int kk = c >> 4, seg = c & 15;
            cp16(bd + (kk * BDSTR + seg * 4) * 4,
                 W + (size_t)(kn + kk) * H + seg * 8);
        }
    };

    loadStage(0, 0); CP_COMMIT();
    loadStage(1, BK); CP_COMMIT();

    int wid = tid >> 5, lane = tid & 31;
    int wr = (wid >> 1) * 64;     // 0,64,128,192
    int wn = (wid & 1) * 64;      // 0 or 64
    int qr = lane >> 2, qc = lane & 3;

    int lRow = lane & 15;
    int lHi  = (lane & 16) ? 4 : 0;
    uint32_t aLane = ((wr + lRow) * ASTR + lHi) * 4;
    uint32_t bLane = (lRow * BDSTR + (wn >> 1) + lHi) * 4;

    float acc[4][8][4];
#pragma unroll
    for (int mt = 0; mt < 4; mt++)
#pragma unroll
        for (int nt = 0; nt < 8; nt++)
#pragma unroll
            for (int i = 0; i < 4; i++) acc[mt][nt][i] = 0.0f;

    const int NIT = F / BK;   // 112
    int s = 0;
    for (int i = 0; i < NIT; i++) {
        CP_WAIT1();
        __syncthreads();

        uint32_t aB = base + (s * DWN_STAGE) * 4 + aLane;
        uint32_t bB = base + (s * DWN_STAGE + A_WORDS) * 4 + bLane;
#pragma unroll
        for (int ks = 0; ks < 2; ks++) {
            uint32_t a[4][4];
#pragma unroll
            for (int mt = 0; mt < 4; mt++)
                ldm_x4(a[mt], aB + (mt * 16 * ASTR + ks * 8) * 4);
            uint32_t bfr[4][4];
#pragma unroll
            for (int ntp = 0; ntp < 4; ntp++)
                ldm_x4t(bfr[ntp], bB + (ks * 16 * BDSTR + ntp * 8) * 4);
#pragma unroll
            for (int mt = 0; mt < 4; mt++)
#pragma unroll
                for (int ntp = 0; ntp < 4; ntp++) {
                    mma16(acc[mt][ntp * 2 + 0], a[mt], &bfr[ntp][0]);
                    mma16(acc[mt][ntp * 2 + 1], a[mt], &bfr[ntp][2]);
                }
        }
        if (i + 2 < NIT) {
            int sn = (s + 2) % 3;
            loadStage(sn, (i + 2) * BK);
        }
        CP_COMMIT();
        s = (s + 1) % 3;
    }

    // weighted scatter
#pragma unroll
    for (int mt = 0; mt < 4; mt++)
#pragma unroll
        for (int nt = 0; nt < 8; nt++) {
            int col = n0 + wn + nt * 8 + 2 * qc;
#pragma unroll
            for (int h = 0; h < 2; h++) {
                int r = row0 + wr + mt * 16 + qr + h * 8;
                if (r >= cnt) continue;
                int tok = g_idx[e * T + r];
                float wgt = g_wt[e * T + r];
                float* yr = y + (size_t)tok * H + col;
                atomicAdd(&yr[0], acc[mt][nt][h * 2 + 0] * wgt);
                atomicAdd(&yr[1], acc[mt][nt][h * 2 + 1] * wgt);
            }
        }
}

// ---------------- launch ----------------
extern "C" void kernel_launch(void* const* d_in, const int* in_sizes, int n_in,
                              void* d_out, int out_size) {
    const float* x     = (const float*)d_in[0];
    const float* gw    = (const float*)d_in[1];
    const float* wup   = (const float*)d_in[2];
    const float* wgate = (const float*)d_in[3];
    const float* wdown = (const float*)d_in[4];
    float* y = (float*)d_out;

    int write_logits = (out_size >= T * H + T * NE) ? 1 : 0;
    float* logits = y + (size_t)T * H;

    __half *wu_h, *wg_h, *wd_h;
    cudaGetSymbolAddress((void**)&wu_h, g_wu_h);
    cudaGetSymbolAddress((void**)&wg_h, g_wg_h);
    cudaGetSymbolAddress((void**)&wd_h, g_wd_h);

    cudaFuncSetAttribute(upgate_kernel, cudaFuncAttributeMaxDynamicSharedMemorySize, SMEM_UPG);
    cudaFuncSetAttribute(down_kernel,   cudaFuncAttributeMaxDynamicSharedMemorySize, SMEM_DWN);

    zero_kernel<<<256, 256>>>(y);
    int nw = NE * H * F / 4;
    cvth_kernel<<<2048, 256>>>((const float4*)wup,   (uint2*)wu_h, nw);
    cvth_kernel<<<2048, 256>>>((const float4*)wgate, (uint2*)wg_h, nw);
    cvth_kernel<<<2048, 256>>>((const float4*)wdown, (uint2*)wd_h, nw);
    router_kernel<<<T / 4, 128>>>(x, gw, logits, write_logits);
    upgate_kernel<<<dim3(NE * MT, F / 64), 256, SMEM_UPG>>>();
    down_kernel<<<dim3(NE * MT, H / 128), 256, SMEM_DWN>>>(y);
}

// round 16
// speedup vs baseline: 1.1115x; 1.1115x over previous
#include <cuda_runtime.h>
#include <cuda_fp16.h>
#include <math.h>
#include <stdint.h>

#define NE 8
#define H 1024
#define F 3584
#define T 4096

#define BM 256
#define BK 64              // halves of K per mainloop iter (4 k16 slices)
#define MT (T / BM)        // 16 m-tiles per expert

// smem strides in 32-bit words (each word = 2 halves)
#define ASTR 36            // 32 data words + 4 pad
#define A_WORDS (BM * ASTR)          // 9216
#define BUSTR 36
#define BU_WORDS (BK * BUSTR)        // 2304
#define BDSTR 68
#define BD_WORDS (BK * BDSTR)        // 4352

// 3-stage pipelines
#define UPG_STAGE (A_WORDS + 2 * BU_WORDS)          // 13824 words (55296 B)
#define DWN_STAGE (A_WORDS + BD_WORDS)              // 13568 words (54272 B)
#define SMEM_UPG (3 * UPG_STAGE * 4)                // 165888 B
#define SMEM_DWN (3 * DWN_STAGE * 4)                // 162816 B

// ---------------- scratch (device globals) ----------------
__device__ int    g_count[NE];
__device__ int    g_idx[NE * T];
__device__ float  g_wt[NE * T];
__device__ __half g_act[(size_t)NE * T * F];
__device__ __half g_wu_h[(size_t)NE * H * F];
__device__ __half g_wg_h[(size_t)NE * H * F];
__device__ __half g_wd_h[(size_t)NE * F * H];
__device__ __half g_x_h[(size_t)T * H];

// ---------------- helpers ----------------
__device__ __forceinline__ uint32_t smem_u32(const void* p) {
    uint32_t a;
    asm("{ .reg .u64 t; cvta.to.shared.u64 t, %1; cvt.u32.u64 %0, t; }" : "=r"(a) : "l"(p));
    return a;
}
__device__ __forceinline__ void cp16(uint32_t dst, const void* src) {
    asm volatile("cp.async.cg.shared.global [%0], [%1], 16;" :: "r"(dst), "l"(src));
}
#define CP_COMMIT() asm volatile("cp.async.commit_group;" ::: "memory")
#define CP_WAIT1()  asm volatile("cp.async.wait_group 1;" ::: "memory")

__device__ __forceinline__ void ldm_x4(uint32_t* r, uint32_t addr) {
    asm volatile("ldmatrix.sync.aligned.m8n8.x4.shared.b16 {%0,%1,%2,%3}, [%4];"
        : "=r"(r[0]), "=r"(r[1]), "=r"(r[2]), "=r"(r[3]) : "r"(addr));
}
__device__ __forceinline__ void ldm_x4t(uint32_t* r, uint32_t addr) {
    asm volatile("ldmatrix.sync.aligned.m8n8.x4.trans.shared.b16 {%0,%1,%2,%3}, [%4];"
        : "=r"(r[0]), "=r"(r[1]), "=r"(r[2]), "=r"(r[3]) : "r"(addr));
}
__device__ __forceinline__ void mma16(float* d, const uint32_t* a, const uint32_t* b) {
    asm volatile(
        "mma.sync.aligned.m16n8k16.row.col.f32.f16.f16.f32 "
        "{%0,%1,%2,%3},{%4,%5,%6,%7},{%8,%9},{%0,%1,%2,%3};"
        : "+f"(d[0]), "+f"(d[1]), "+f"(d[2]), "+f"(d[3])
        : "r"(a[0]), "r"(a[1]), "r"(a[2]), "r"(a[3]), "r"(b[0]), "r"(b[1]));
}

// ---------------- kernel 0: zero y + counters ----------------
__global__ void zero_kernel(float* __restrict__ y) {
    size_t n = (size_t)T * H;
    size_t stride = (size_t)gridDim.x * blockDim.x;
    for (size_t i = (size_t)blockIdx.x * blockDim.x + threadIdx.x; i < n; i += stride)
        y[i] = 0.0f;
    if (blockIdx.x == 0 && threadIdx.x < NE) g_count[threadIdx.x] = 0;
}

// ---------------- kernel: fp32 -> fp16 pre-convert (weights) ----------------
__global__ void cvth_kernel(const float4* __restrict__ src, uint2* __restrict__ dst, int n4) {
    int stride = gridDim.x * blockDim.x;
    for (int i = blockIdx.x * blockDim.x + threadIdx.x; i < n4; i += stride) {
        float4 v = src[i];
        __half2 h0 = __floats2half2_rn(v.x, v.y);
        __half2 h1 = __floats2half2_rn(v.z, v.w);
        uint2 o;
        o.x = *(uint32_t*)&h0;
        o.y = *(uint32_t*)&h1;
        dst[i] = o;
    }
}

// ---------------- kernel 1: router (fp32) + x fp16 convert fused ----------------
__global__ void router_kernel(const float* __restrict__ x,
                              const float* __restrict__ gw,
                              float* __restrict__ logits_out,
                              int write_logits) {
    int warp = threadIdx.x >> 5;
    int lane = threadIdx.x & 31;
    int t = blockIdx.x * 4 + warp;
    if (t >= T) return;
    const float* xr = x + (size_t)t * H;
    __half* xh = g_x_h + (size_t)t * H;

    float acc[NE];
#pragma unroll
    for (int e = 0; e < NE; e++) acc[e] = 0.0f;
    for (int k = lane; k < H; k += 32) {
        float xv = xr[k];
        xh[k] = __float2half_rn(xv);
        const float* g = gw + (size_t)k * NE;
#pragma unroll
        for (int e = 0; e < NE; e++) acc[e] += xv * g[e];
    }
#pragma unroll
    for (int off = 16; off > 0; off >>= 1)
#pragma unroll
        for (int e = 0; e < NE; e++)
            acc[e] += __shfl_down_sync(0xffffffffu, acc[e], off);

    if (lane == 0) {
        if (write_logits) {
#pragma unroll
            for (int e = 0; e < NE; e++) logits_out[(size_t)t * NE + e] = acc[e];
        }
        int i1 = 0;
#pragma unroll
        for (int e = 1; e < NE; e++) if (acc[e] > acc[i1]) i1 = e;
        int i2 = (i1 == 0) ? 1 : 0;
#pragma unroll
        for (int e = 0; e < NE; e++)
            if (e != i1 && acc[e] > acc[i2]) i2 = e;
        float w1 = 1.0f / (1.0f + expf(acc[i2] - acc[i1]));
        float w2 = 1.0f / (1.0f + expf(acc[i1] - acc[i2]));
        int p1 = atomicAdd(&g_count[i1], 1);
        g_idx[i1 * T + p1] = t; g_wt[i1 * T + p1] = w1;
        int p2 = atomicAdd(&g_count[i2], 1);
        g_idx[i2 * T + p2] = t; g_wt[i2 * T + p2] = w2;
    }
}

// ---------------- kernel 2: fp16 up+gate GEMM + SiLU ----------------
// 512 threads, 16 warps (8 m x 2 n), block tile 256x64 per matrix,
// warp tile 32x32 per matrix. BK=64, 3-stage cp.async pipeline, 1 CTA/SM.
__global__ __launch_bounds__(512, 1) void upgate_kernel() {
    extern __shared__ uint32_t sm[];
    __shared__ int toks[BM];

    int e = blockIdx.x / MT;
    int mtile = blockIdx.x % MT;
    int cnt = g_count[e];
    int row0 = mtile * BM;
    if (row0 >= cnt) return;
    int f0 = blockIdx.y * 64;

    int tid = threadIdx.x;
    if (tid < BM) {
        int r = row0 + tid;
        toks[tid] = (r < cnt) ? g_idx[e * T + r] : g_idx[e * T];
    }
    __syncthreads();

    const __half* Wu = g_wu_h + (size_t)e * H * F + f0;
    const __half* Wg = g_wg_h + (size_t)e * H * F + f0;

    uint32_t base = smem_u32(sm);

    auto loadStage = [&](int s, int kn) {
        uint32_t ad = base + (s * UPG_STAGE) * 4;
        uint32_t ud = ad + A_WORDS * 4;
        uint32_t gd = ud + BU_WORDS * 4;
        // A: 256 rows x 8 chunks (16B = 8 halves) = 2048 -> 4/thread
#pragma unroll
        for (int j = 0; j < 4; j++) {
            int c = tid + j * 512;
            int m = c >> 3, seg = c & 7;
            cp16(ad + (m * ASTR + seg * 4) * 4,
                 g_x_h + (size_t)toks[m] * H + kn + seg * 8);
        }
        // B: 64 k-rows x 8 chunks = 512 per mat -> 1/thread each
        {
            int kk = tid >> 3, seg = tid & 7;
            uint32_t off = (kk * BUSTR + seg * 4) * 4;
            size_t gi = (size_t)(kn + kk) * F + seg * 8;
            cp16(ud + off, Wu + gi);
            cp16(gd + off, Wg + gi);
        }
    };

    loadStage(0, 0); CP_COMMIT();
    loadStage(1, BK); CP_COMMIT();

    int wid = tid >> 5, lane = tid & 31;
    int wr = (wid >> 1) * 32;      // 0..224 (8 m-warps)
    int wn = (wid & 1) * 32;       // 0 or 32
    int qr = lane >> 2, qc = lane & 3;

    int lRow = lane & 15;
    int lHi  = (lane & 16) ? 4 : 0;
    uint32_t aLane = ((wr + lRow) * ASTR + lHi) * 4;
    uint32_t bLane = (lRow * BUSTR + (wn >> 1) + lHi) * 4;

    float accU[2][4][4], accG[2][4][4];
#pragma unroll
    for (int mt = 0; mt < 2; mt++)
#pragma unroll
        for (int nt = 0; nt < 4; nt++)
#pragma unroll
            for (int i = 0; i < 4; i++) { accU[mt][nt][i] = 0.0f; accG[mt][nt][i] = 0.0f; }

    const int NIT = H / BK;   // 16
    int s = 0;
    for (int i = 0; i < NIT; i++) {
        CP_WAIT1();
        __syncthreads();

        uint32_t aB = base + (s * UPG_STAGE) * 4 + aLane;
        uint32_t uB = base + (s * UPG_STAGE + A_WORDS) * 4 + bLane;
        uint32_t gB = base + (s * UPG_STAGE + A_WORDS + BU_WORDS) * 4 + bLane;
#pragma unroll
        for (int ks = 0; ks < 4; ks++) {
            uint32_t a[2][4];
#pragma unroll
            for (int mt = 0; mt < 2; mt++)
                ldm_x4(a[mt], aB + (mt * 16 * ASTR + ks * 8) * 4);
            uint32_t bu[2][4], bg[2][4];
#pragma unroll
            for (int ntp = 0; ntp < 2; ntp++) {
                uint32_t koff = (ks * 16 * BUSTR + ntp * 8) * 4;
                ldm_x4t(bu[ntp], uB + koff);
                ldm_x4t(bg[ntp], gB + koff);
            }
#pragma unroll
            for (int mt = 0; mt < 2; mt++)
#pragma unroll
                for (int ntp = 0; ntp < 2; ntp++) {
                    mma16(accU[mt][ntp * 2 + 0], a[mt], &bu[ntp][0]);
                    mma16(accU[mt][ntp * 2 + 1], a[mt], &bu[ntp][2]);
                    mma16(accG[mt][ntp * 2 + 0], a[mt], &bg[ntp][0]);
                    mma16(accG[mt][ntp * 2 + 1], a[mt], &bg[ntp][2]);
                }
        }
        if (i + 2 < NIT) {
            int sn = (s + 2) % 3;
            loadStage(sn, (i + 2) * BK);
        }
        CP_COMMIT();
        s = (s + 1) % 3;
    }

    // epilogue: silu(up)*gate -> g_act (fp16)
#pragma unroll
    for (int mt = 0; mt < 2; mt++)
#pragma unroll
        for (int nt = 0; nt < 4; nt++) {
            int col = f0 + wn + nt * 8 + 2 * qc;
#pragma unroll
            for (int h = 0; h < 2; h++) {
                int r = row0 + wr + mt * 16 + qr + h * 8;
                if (r >= cnt) continue;
                float u0 = accU[mt][nt][h * 2 + 0], u1 = accU[mt][nt][h * 2 + 1];
                float g0 = accG[mt][nt][h * 2 + 0], g1 = accG[mt][nt][h * 2 + 1];
                float s0 = u0 / (1.0f + expf(-u0)) * g0;
                float s1 = u1 / (1.0f + expf(-u1)) * g1;
                *(__half2*)(g_act + ((size_t)e * T + r) * F + col) = __floats2half2_rn(s0, s1);
            }
        }
}

// ---------------- kernel 3: fp16 down GEMM + weighted scatter ----------------
// 512 threads, 16 warps (8 m x 2 n), block tile 256x128, warp tile 32x64.
// BK=64, 3-stage pipeline, 1 CTA/SM.
__global__ __launch_bounds__(512, 1) void down_kernel(float* __restrict__ y) {
    extern __shared__ uint32_t sm[];

    int e = blockIdx.x / MT;
    int mtile = blockIdx.x % MT;
    int cnt = g_count[e];
    int row0 = mtile * BM;
    if (row0 >= cnt) return;
    int n0 = blockIdx.y * 128;

    const __half* A = g_act + ((size_t)e * T + row0) * F;
    const __half* W = g_wd_h + (size_t)e * F * H + n0;

    int tid = threadIdx.x;
    uint32_t base = smem_u32(sm);

    auto loadStage = [&](int s, int kn) {
        uint32_t ad = base + (s * DWN_STAGE) * 4;
        uint32_t bd = ad + A_WORDS * 4;
        // A: 2048 chunks -> 4/thread
#pragma unroll
        for (int j = 0; j < 4; j++) {
            int c = tid + j * 512;
            int m = c >> 3, seg = c & 7;
            cp16(ad + (m * ASTR + seg * 4) * 4,
                 A + (size_t)m * F + kn + seg * 8);
        }
        // B: 64 k-rows x 16 chunks = 1024 -> 2/thread
#pragma unroll
        for (int j = 0; j < 2; j++) {
            int c = tid + j * 512;
            int kk = c >> 4, seg = c & 15;
            cp16(bd + (kk * BDSTR + seg * 4) * 4,
                 W + (size_t)(kn + kk) * H + seg * 8);
        }
    };

    loadStage(0, 0); CP_COMMIT();
    loadStage(1, BK); CP_COMMIT();

    int wid = tid >> 5, lane = tid & 31;
    int wr = (wid >> 1) * 32;     // 0..224
    int wn = (wid & 1) * 64;      // 0 or 64
    int qr = lane >> 2, qc = lane & 3;

    int lRow = lane & 15;
    int lHi  = (lane & 16) ? 4 : 0;
    uint32_t aLane = ((wr + lRow) * ASTR + lHi) * 4;
    uint32_t bLane = (lRow * BDSTR + (wn >> 1) + lHi) * 4;

    float acc[2][8][4];
#pragma unroll
    for (int mt = 0; mt < 2; mt++)
#pragma unroll
        for (int nt = 0; nt < 8; nt++)
#pragma unroll
            for (int i = 0; i < 4; i++) acc[mt][nt][i] = 0.0f;

    const int NIT = F / BK;   // 56
    int s = 0;
    for (int i = 0; i < NIT; i++) {
        CP_WAIT1();
        __syncthreads();

        uint32_t aB = base + (s * DWN_STAGE) * 4 + aLane;
        uint32_t bB = base + (s * DWN_STAGE + A_WORDS) * 4 + bLane;
#pragma unroll
        for (int ks = 0; ks < 4; ks++) {
            uint32_t a[2][4];
#pragma unroll
            for (int mt = 0; mt < 2; mt++)
                ldm_x4(a[mt], aB + (mt * 16 * ASTR + ks * 8) * 4);
            uint32_t bfr[4][4];
#pragma unroll
            for (int ntp = 0; ntp < 4; ntp++)
                ldm_x4t(bfr[ntp], bB + (ks * 16 * BDSTR + ntp * 8) * 4);
#pragma unroll
            for (int mt = 0; mt < 2; mt++)
#pragma unroll
                for (int ntp = 0; ntp < 4; ntp++) {
                    mma16(acc[mt][ntp * 2 + 0], a[mt], &bfr[ntp][0]);
                    mma16(acc[mt][ntp * 2 + 1], a[mt], &bfr[ntp][2]);
                }
        }
        if (i + 2 < NIT) {
            int sn = (s + 2) % 3;
            loadStage(sn, (i + 2) * BK);
        }
        CP_COMMIT();
        s = (s + 1) % 3;
    }

    // weighted scatter
#pragma unroll
    for (int mt = 0; mt < 2; mt++)
#pragma unroll
        for (int nt = 0; nt < 8; nt++) {
            int col = n0 + wn + nt * 8 + 2 * qc;
#pragma unroll
            for (int h = 0; h < 2; h++) {
                int r = row0 + wr + mt * 16 + qr + h * 8;
                if (r >= cnt) continue;
                int tok = g_idx[e * T + r];
                float wgt = g_wt[e * T + r];
                float* yr = y + (size_t)tok * H + col;
                atomicAdd(&yr[0], acc[mt][nt][h * 2 + 0] * wgt);
                atomicAdd(&yr[1], acc[mt][nt][h * 2 + 1] * wgt);
            }
        }
}

// ---------------- launch ----------------
extern "C" void kernel_launch(void* const* d_in, const int* in_sizes, int n_in,
                              void* d_out, int out_size) {
    const float* x     = (const float*)d_in[0];
    const float* gw    = (const float*)d_in[1];
    const float* wup   = (const float*)d_in[2];
    const float* wgate = (const float*)d_in[3];
    const float* wdown = (const float*)d_in[4];
    float* y = (float*)d_out;

    int write_logits = (out_size >= T * H + T * NE) ? 1 : 0;
    float* logits = y + (size_t)T * H;

    __half *wu_h, *wg_h, *wd_h;
    cudaGetSymbolAddress((void**)&wu_h, g_wu_h);
    cudaGetSymbolAddress((void**)&wg_h, g_wg_h);
    cudaGetSymbolAddress((void**)&wd_h, g_wd_h);

    cudaFuncSetAttribute(upgate_kernel, cudaFuncAttributeMaxDynamicSharedMemorySize, SMEM_UPG);
    cudaFuncSetAttribute(down_kernel,   cudaFuncAttributeMaxDynamicSharedMemorySize, SMEM_DWN);

    zero_kernel<<<256, 256>>>(y);
    int nw = NE * H * F / 4;
    cvth_kernel<<<2048, 256>>>((const float4*)wup,   (uint2*)wu_h, nw);
    cvth_kernel<<<2048, 256>>>((const float4*)wgate, (uint2*)wg_h, nw);
    cvth_kernel<<<2048, 256>>>((const float4*)wdown, (uint2*)wd_h, nw);
    router_kernel<<<T / 4, 128>>>(x, gw, logits, write_logits);
    upgate_kernel<<<dim3(NE * MT, F / 64), 512, SMEM_UPG>>>();
    down_kernel<<<dim3(NE * MT, H / 128), 512, SMEM_DWN>>>(y);
}